// round 9
// baseline (speedup 1.0000x reference)
#include <cuda_runtime.h>
#include <math.h>

// Problem constants
#define B_      32
#define T_      1024
#define INCH    3
#define CD      12          // path channels: 1 time + 3 orig + 8 aug
#define SIGC    1884        // 12 + 144 + 1728
#define SIGPAD  1888        // padded shared stride
#define NBG     64          // B * G paths
#define CH_STEPS 32
#define NCHUNK  32          // chunks per path
#define NSTEPS  1023
#define DT_     (1.0f/1023.0f)
#define MIDS_PER_PATH 8     // 32 chunks / 4 per block

// Scratch (static device arrays — no allocation)
__device__ __align__(16) float g_mid[512 * SIGC];   // 8 per path, ~3.9 MB
__device__ __align__(16) float g_sig[NBG * SIGC];

typedef unsigned long long ull;

__device__ __forceinline__ ull pack2(float a, float b) {
    ull r;
    asm("mov.b64 %0, {%1,%2};" : "=l"(r) : "f"(a), "f"(b));
    return r;
}
__device__ __forceinline__ void ffma2(ull& d, ull a, ull b) {
    asm("fma.rn.f32x2 %0, %1, %2, %0;" : "+l"(d) : "l"(a), "l"(b));
}
union U64F2 { ull u; float2 f; };

// ---------------------------------------------------------------------------
// Kernel 1: 4 chunks (32 steps each) per block, 72 threads per chunk,
// fused level-1 Chen combine of the 4 chunks.
// Per-thread: i = wt/6, owns j0=2m, j1=2m+1 (m = wt%6).
// Per-step collapsed update (packed f32x2):
//   u  = di/6 + s1/2 ;  c3pair = s2pair + u*djpair
//   S3[i][j0..1][:] += c3_j * d[:]                       (12 FFMA2)
//   v  = s1 + di/2   ;  s2pair += v*djpair
//   s1 += di
// ---------------------------------------------------------------------------
__global__ __launch_bounds__(288) void sig_chunk4_kernel(
    const float* __restrict__ x, const float* __restrict__ aug_w)
{
    __shared__ __align__(16) float sh_d[4][CH_STEPS * CD];   // 6 KB
    __shared__ __align__(16) float sh_sig[4][SIGPAD];        // 30.2 KB
    __shared__ float sh_w[4][24];

    int tid = threadIdx.x;
    int sub = tid / 72;
    int wt  = tid - sub * 72;               // 0..71
    int chunk = blockIdx.x * 4 + sub;       // 0..2047
    int bg = chunk >> 5;                    // path id
    int c  = chunk & 31;
    int b  = bg >> 1;
    int g  = bg & 1;
    int t0 = c * CH_STEPS;
    int L  = min(CH_STEPS, NSTEPS - t0);    // 32, last chunk of path: 31

    if (wt < 24) sh_w[sub][wt] = aug_w[g * 24 + wt];
    __syncthreads();

    // increments: d[t] = [dt, dx0..2, W_g*dx]  (aug bias cancels)
    if (wt < L) {
        const float* xp = x + ((size_t)b * T_ + (t0 + wt)) * INCH;
        float dx0 = xp[3] - xp[0];
        float dx1 = xp[4] - xp[1];
        float dx2 = xp[5] - xp[2];
        float* dr = sh_d[sub] + wt * CD;
        dr[0] = DT_; dr[1] = dx0; dr[2] = dx1; dr[3] = dx2;
        const float* w = sh_w[sub];
#pragma unroll
        for (int e = 0; e < 8; e++)
            dr[4 + e] = w[e*3]*dx0 + w[e*3+1]*dx1 + w[e*3+2]*dx2;
    }
    __syncthreads();

    int i = wt / 6;
    int m = wt - i * 6;

    float s1 = 0.f;
    ull s2p = 0ull;
    ull s3a[6], s3b[6];
#pragma unroll
    for (int q = 0; q < 6; q++) { s3a[q] = 0ull; s3b[q] = 0ull; }

    const float* drbase = sh_d[sub];
#pragma unroll 2
    for (int t = 0; t < L; t++) {
        const float* dr = drbase + t * CD;
        const ulonglong2* qv = (const ulonglong2*)dr;
        ulonglong2 qa = qv[0];
        ulonglong2 qb = qv[1];
        ulonglong2 qc = qv[2];
        float di = dr[i];
        ull djp = *(const ull*)(dr + 2 * m);       // (d_{j0}, d_{j1})

        float u = fmaf(di, (1.f/6.f), 0.5f * s1);
        ull c3p = s2p;
        ffma2(c3p, pack2(u, u), djp);
        U64F2 cu; cu.u = c3p;
        ull cc0 = pack2(cu.f.x, cu.f.x);
        ull cc1 = pack2(cu.f.y, cu.f.y);

        ffma2(s3a[0], cc0, qa.x); ffma2(s3a[1], cc0, qa.y);
        ffma2(s3a[2], cc0, qb.x); ffma2(s3a[3], cc0, qb.y);
        ffma2(s3a[4], cc0, qc.x); ffma2(s3a[5], cc0, qc.y);
        ffma2(s3b[0], cc1, qa.x); ffma2(s3b[1], cc1, qa.y);
        ffma2(s3b[2], cc1, qb.x); ffma2(s3b[3], cc1, qb.y);
        ffma2(s3b[4], cc1, qc.x); ffma2(s3b[5], cc1, qc.y);

        float v = fmaf(di, 0.5f, s1);
        ffma2(s2p, pack2(v, v), djp);
        s1 += di;
    }

    // Store this chunk's signature into shared staging (signatory layout)
    {
        float* out = sh_sig[sub];
        if (m == 0) out[i] = s1;
        U64F2 s2u; s2u.u = s2p;
        out[12 + i*12 + 2*m]     = s2u.f.x;
        out[12 + i*12 + 2*m + 1] = s2u.f.y;
        float* o3 = out + 156 + (i*12 + 2*m) * 12;   // row j0, then row j1
        U64F2 w0, w1, w2, w3, w4, w5;
        w0.u = s3a[0]; w1.u = s3a[1]; w2.u = s3a[2];
        w3.u = s3a[3]; w4.u = s3a[4]; w5.u = s3a[5];
        *(float4*)(o3)     = make_float4(w0.f.x, w0.f.y, w1.f.x, w1.f.y);
        *(float4*)(o3 + 4) = make_float4(w2.f.x, w2.f.y, w3.f.x, w3.f.y);
        *(float4*)(o3 + 8) = make_float4(w4.f.x, w4.f.y, w5.f.x, w5.f.y);
        w0.u = s3b[0]; w1.u = s3b[1]; w2.u = s3b[2];
        w3.u = s3b[3]; w4.u = s3b[4]; w5.u = s3b[5];
        *(float4*)(o3 + 12) = make_float4(w0.f.x, w0.f.y, w1.f.x, w1.f.y);
        *(float4*)(o3 + 16) = make_float4(w2.f.x, w2.f.y, w3.f.x, w3.f.y);
        *(float4*)(o3 + 20) = make_float4(w4.f.x, w4.f.y, w5.f.x, w5.f.y);
    }
    __syncthreads();

    // Fused level-1 Chen combine (4 chunks -> 1), threads 0..143
    if (tid < 144) {
        int ci = tid / 12;
        int cj = tid - ci * 12;

        float a1 = sh_sig[0][ci];
        float a2 = sh_sig[0][12 + tid];
        float a3[12];
        {
            const float* p = sh_sig[0] + 156 + tid * 12;
            float4 v0 = *(const float4*)p;
            float4 v1 = *(const float4*)(p + 4);
            float4 v2 = *(const float4*)(p + 8);
            a3[0]=v0.x; a3[1]=v0.y; a3[2]=v0.z;  a3[3]=v0.w;
            a3[4]=v1.x; a3[5]=v1.y; a3[6]=v1.z;  a3[7]=v1.w;
            a3[8]=v2.x; a3[9]=v2.y; a3[10]=v2.z; a3[11]=v2.w;
        }

#pragma unroll
        for (int cc = 1; cc < 4; cc++) {
            const float* Bp = sh_sig[cc];
            float4 b1a = *(const float4*)(Bp);
            float4 b1b = *(const float4*)(Bp + 4);
            float4 b1c = *(const float4*)(Bp + 8);
            float b1i = Bp[ci];
            float b1j = Bp[cj];
            float b2s = Bp[12 + tid];
            const float* r2 = Bp + 12 + cj * 12;
            float4 r2a = *(const float4*)(r2);
            float4 r2b = *(const float4*)(r2 + 4);
            float4 r2c = *(const float4*)(r2 + 8);
            const float* p3 = Bp + 156 + tid * 12;
            float4 b3a = *(const float4*)(p3);
            float4 b3b = *(const float4*)(p3 + 4);
            float4 b3c = *(const float4*)(p3 + 8);

            a3[0]  += b3a.x + a1*r2a.x + a2*b1a.x;
            a3[1]  += b3a.y + a1*r2a.y + a2*b1a.y;
            a3[2]  += b3a.z + a1*r2a.z + a2*b1a.z;
            a3[3]  += b3a.w + a1*r2a.w + a2*b1a.w;
            a3[4]  += b3b.x + a1*r2b.x + a2*b1b.x;
            a3[5]  += b3b.y + a1*r2b.y + a2*b1b.y;
            a3[6]  += b3b.z + a1*r2b.z + a2*b1b.z;
            a3[7]  += b3b.w + a1*r2b.w + a2*b1b.w;
            a3[8]  += b3c.x + a1*r2c.x + a2*b1c.x;
            a3[9]  += b3c.y + a1*r2c.y + a2*b1c.y;
            a3[10] += b3c.z + a1*r2c.z + a2*b1c.z;
            a3[11] += b3c.w + a1*r2c.w + a2*b1c.w;
            a2 += b2s + a1 * b1j;     // uses OLD a1
            a1 += b1i;
        }

        float* out = g_mid + (size_t)blockIdx.x * SIGC;
        if (cj == 0) out[ci] = a1;
        out[12 + tid] = a2;
        float* o3 = out + 156 + tid * 12;
        *(float4*)(o3)     = make_float4(a3[0], a3[1], a3[2], a3[3]);
        *(float4*)(o3 + 4) = make_float4(a3[4], a3[5], a3[6], a3[7]);
        *(float4*)(o3 + 8) = make_float4(a3[8], a3[9], a3[10], a3[11]);
    }
}

// ---------------------------------------------------------------------------
// Kernel 2: level-2 Chen combine (8 mids -> final signature per path)
// ---------------------------------------------------------------------------
__global__ __launch_bounds__(160) void sig_combine2_kernel()
{
    int tid = threadIdx.x;
    if (tid >= 144) return;
    int i = tid / 12;
    int j = tid - i * 12;

    const float* base = g_mid + (size_t)blockIdx.x * MIDS_PER_PATH * SIGC;

    float a1 = base[i];
    float a2 = base[12 + tid];
    float a3[12];
    {
        const float* p = base + 156 + tid * 12;
        float4 v0 = *(const float4*)p;
        float4 v1 = *(const float4*)(p + 4);
        float4 v2 = *(const float4*)(p + 8);
        a3[0]=v0.x; a3[1]=v0.y; a3[2]=v0.z;  a3[3]=v0.w;
        a3[4]=v1.x; a3[5]=v1.y; a3[6]=v1.z;  a3[7]=v1.w;
        a3[8]=v2.x; a3[9]=v2.y; a3[10]=v2.z; a3[11]=v2.w;
    }

#pragma unroll
    for (int c = 1; c < MIDS_PER_PATH; c++) {
        const float* Bp = base + (size_t)c * SIGC;
        float4 b1a = *(const float4*)(Bp);
        float4 b1b = *(const float4*)(Bp + 4);
        float4 b1c = *(const float4*)(Bp + 8);
        float b1i = Bp[i];
        float b1j = Bp[j];
        float b2s = Bp[12 + tid];
        const float* r2 = Bp + 12 + j * 12;
        float4 r2a = *(const float4*)(r2);
        float4 r2b = *(const float4*)(r2 + 4);
        float4 r2c = *(const float4*)(r2 + 8);
        const float* p3 = Bp + 156 + tid * 12;
        float4 b3a = *(const float4*)(p3);
        float4 b3b = *(const float4*)(p3 + 4);
        float4 b3c = *(const float4*)(p3 + 8);

        a3[0]  += b3a.x + a1*r2a.x + a2*b1a.x;
        a3[1]  += b3a.y + a1*r2a.y + a2*b1a.y;
        a3[2]  += b3a.z + a1*r2a.z + a2*b1a.z;
        a3[3]  += b3a.w + a1*r2a.w + a2*b1a.w;
        a3[4]  += b3b.x + a1*r2b.x + a2*b1b.x;
        a3[5]  += b3b.y + a1*r2b.y + a2*b1b.y;
        a3[6]  += b3b.z + a1*r2b.z + a2*b1b.z;
        a3[7]  += b3b.w + a1*r2b.w + a2*b1b.w;
        a3[8]  += b3c.x + a1*r2c.x + a2*b1c.x;
        a3[9]  += b3c.y + a1*r2c.y + a2*b1c.y;
        a3[10] += b3c.z + a1*r2c.z + a2*b1c.z;
        a3[11] += b3c.w + a1*r2c.w + a2*b1c.w;
        a2 += b2s + a1 * b1j;
        a1 += b1i;
    }

    float* out = g_sig + (size_t)blockIdx.x * SIGC;
    if (j == 0) out[i] = a1;
    out[12 + tid] = a2;
    float* o3 = out + 156 + tid * 12;
    *(float4*)(o3)     = make_float4(a3[0], a3[1], a3[2], a3[3]);
    *(float4*)(o3 + 4) = make_float4(a3[4], a3[5], a3[6], a3[7]);
    *(float4*)(o3 + 8) = make_float4(a3[8], a3[9], a3[10], a3[11]);
}

// ---------------------------------------------------------------------------
// Kernel 3: one block per output element (b,o):
//   out[b][o] = sigmoid( sig[b] . lin_w[o] + lin_b[o] )
// ---------------------------------------------------------------------------
#define SIG2  (2 * SIGC)        // 3768
#define SIG2V (SIG2 / 4)        // 942 float4s

__global__ __launch_bounds__(128) void sig_out_kernel(
    const float* __restrict__ lin_w, const float* __restrict__ lin_b,
    float* __restrict__ out)
{
    int b = blockIdx.x >> 5;
    int o = blockIdx.x & 31;
    int tid = threadIdx.x;

    const float4* wr = (const float4*)(lin_w + (size_t)o * SIG2);
    const float4* sg = (const float4*)(g_sig + (size_t)b * SIG2);

    float acc = 0.f;
#pragma unroll
    for (int it = 0; it < 8; it++) {
        int m = tid + it * 128;
        if (m < SIG2V) {
            float4 w = __ldg(wr + m);
            float4 s = __ldg(sg + m);
            acc = fmaf(w.x, s.x, acc);
            acc = fmaf(w.y, s.y, acc);
            acc = fmaf(w.z, s.z, acc);
            acc = fmaf(w.w, s.w, acc);
        }
    }

#pragma unroll
    for (int off = 16; off; off >>= 1)
        acc += __shfl_down_sync(0xffffffffu, acc, off);

    __shared__ float sh[4];
    int warp = tid >> 5;
    int lane = tid & 31;
    if (lane == 0) sh[warp] = acc;
    __syncthreads();

    if (tid == 0) {
        float z = sh[0] + sh[1] + sh[2] + sh[3] + lin_b[o];
        out[b * 32 + o] = 1.0f / (1.0f + expf(-z));
    }
}

// ---------------------------------------------------------------------------
extern "C" void kernel_launch(void* const* d_in, const int* in_sizes, int n_in,
                              void* d_out, int out_size)
{
    const float* x     = (const float*)d_in[0];  // (32,1024,3)
    const float* aug_w = (const float*)d_in[1];  // (2,8,3)
    // d_in[2] = aug_b — unused (bias cancels in path increments)
    const float* lin_w = (const float*)d_in[3];  // (32, 3768)
    const float* lin_b = (const float*)d_in[4];  // (32,)
    float* out = (float*)d_out;                  // (32,32)

    sig_chunk4_kernel<<<512, 288>>>(x, aug_w);
    sig_combine2_kernel<<<NBG, 160>>>();
    sig_out_kernel<<<B_ * 32, 128>>>(lin_w, lin_b, out);
}

// round 10
// speedup vs baseline: 1.0014x; 1.0014x over previous
#include <cuda_runtime.h>
#include <math.h>

// Problem constants
#define B_      32
#define T_      1024
#define INCH    3
#define CD      12          // path channels: 1 time + 3 orig + 8 aug
#define SIGC    1884        // 12 + 144 + 1728
#define SIGPAD  1888        // padded shared stride
#define NBG     64          // B * G paths
#define CH_STEPS 32
#define NSTEPS  1023
#define DT_     (1.0f/1023.0f)
#define MIDS_PER_PATH 8     // 32 chunks / 4 per block

// Scratch (static device arrays — no allocation)
__device__ __align__(16) float g_mid[512 * SIGC];   // 8 per path, ~3.9 MB
__device__ __align__(16) float g_sig[NBG * SIGC];

typedef unsigned long long ull;

__device__ __forceinline__ ull pack2(float a, float b) {
    ull r;
    asm("mov.b64 %0, {%1,%2};" : "=l"(r) : "f"(a), "f"(b));
    return r;
}
__device__ __forceinline__ void ffma2(ull& d, ull a, ull b) {
    asm("fma.rn.f32x2 %0, %1, %2, %0;" : "+l"(d) : "l"(a), "l"(b));
}
union U64F2 { ull u; float2 f; };

// ---------------------------------------------------------------------------
// Kernel 1: 4 chunks (32 steps) per block, 36 threads per chunk.
// Thread owns (i, j = 4mm..4mm+3): i = wt/3, mm = wt%3.
// Per step: 5 LDS serve 24 S3-FFMA2s (2x the work per LDS vs 72-thread layout).
//   u = di/6 + s1/2 ; c3(pairs) = s2(pairs) + u*dj(pairs)
//   S3[i][j][:] += c3_j * d[:]        (4 rows x 6 FFMA2)
//   v = s1 + di/2  ; s2(pairs) += v*dj(pairs) ; s1 += di
// Then fused level-1 Chen combine of the 4 chunks (all 144 threads).
// ---------------------------------------------------------------------------
__global__ __launch_bounds__(144) void sig_chunk4_kernel(
    const float* __restrict__ x, const float* __restrict__ aug_w)
{
    __shared__ __align__(16) float sh_d[4][CH_STEPS * CD];   // 6 KB
    __shared__ __align__(16) float sh_sig[4][SIGPAD];        // 30.2 KB
    __shared__ float sh_w[4][24];

    int tid = threadIdx.x;
    int sub = tid / 36;
    int wt  = tid - sub * 36;               // 0..35
    int chunk = blockIdx.x * 4 + sub;       // 0..2047
    int bg = chunk >> 5;                    // path id
    int c  = chunk & 31;
    int t0 = c * CH_STEPS;
    int L  = min(CH_STEPS, NSTEPS - t0);    // 32, last chunk of path: 31
    int g  = bg & 1;

    if (wt < 24) sh_w[sub][wt] = aug_w[g * 24 + wt];
    __syncthreads();

    // increments: d[t] = [dt, dx0..2, W_g*dx]  (aug bias cancels)
    // row mapping over the whole block: tid<128 -> (sub2 = tid/32, step = tid%32)
    {
        int sub2 = tid >> 5;
        int st   = tid & 31;
        if (sub2 < 4) {
            int chunk2 = blockIdx.x * 4 + sub2;
            int bg2 = chunk2 >> 5;
            int c2  = chunk2 & 31;
            int b2  = bg2 >> 1;
            int t02 = c2 * CH_STEPS;
            if (t02 + st < NSTEPS) {
                const float* xp = x + ((size_t)b2 * T_ + (t02 + st)) * INCH;
                float dx0 = xp[3] - xp[0];
                float dx1 = xp[4] - xp[1];
                float dx2 = xp[5] - xp[2];
                float* dr = sh_d[sub2] + st * CD;
                dr[0] = DT_; dr[1] = dx0; dr[2] = dx1; dr[3] = dx2;
                const float* w = sh_w[sub2];
#pragma unroll
                for (int e = 0; e < 8; e++)
                    dr[4 + e] = w[e*3]*dx0 + w[e*3+1]*dx1 + w[e*3+2]*dx2;
            }
        }
    }
    __syncthreads();

    int i  = wt / 3;            // 0..11
    int mm = wt - i * 3;        // 0..2 -> j rows 4mm..4mm+3

    float s1 = 0.f;
    ull s2p0 = 0ull, s2p1 = 0ull;
    ull sA[6], sB[6], sC[6], sD[6];
#pragma unroll
    for (int q = 0; q < 6; q++) { sA[q]=0ull; sB[q]=0ull; sC[q]=0ull; sD[q]=0ull; }

    const float* drbase = sh_d[sub];
#pragma unroll 2
    for (int t = 0; t < L; t++) {
        const float* dr = drbase + t * CD;
        const ulonglong2* qv = (const ulonglong2*)dr;
        ulonglong2 qa = qv[0];
        ulonglong2 qb = qv[1];
        ulonglong2 qc = qv[2];
        float di = dr[i];
        ulonglong2 dj = *(const ulonglong2*)(dr + 4 * mm);   // 16B-aligned

        float u = fmaf(di, (1.f/6.f), 0.5f * s1);
        ull u2 = pack2(u, u);
        ull c3p0 = s2p0; ffma2(c3p0, u2, dj.x);
        ull c3p1 = s2p1; ffma2(c3p1, u2, dj.y);
        U64F2 ca; ca.u = c3p0;
        U64F2 cb; cb.u = c3p1;
        ull ccA = pack2(ca.f.x, ca.f.x);
        ull ccB = pack2(ca.f.y, ca.f.y);
        ull ccC = pack2(cb.f.x, cb.f.x);
        ull ccD = pack2(cb.f.y, cb.f.y);

        ffma2(sA[0], ccA, qa.x); ffma2(sA[1], ccA, qa.y);
        ffma2(sA[2], ccA, qb.x); ffma2(sA[3], ccA, qb.y);
        ffma2(sA[4], ccA, qc.x); ffma2(sA[5], ccA, qc.y);
        ffma2(sB[0], ccB, qa.x); ffma2(sB[1], ccB, qa.y);
        ffma2(sB[2], ccB, qb.x); ffma2(sB[3], ccB, qb.y);
        ffma2(sB[4], ccB, qc.x); ffma2(sB[5], ccB, qc.y);
        ffma2(sC[0], ccC, qa.x); ffma2(sC[1], ccC, qa.y);
        ffma2(sC[2], ccC, qb.x); ffma2(sC[3], ccC, qb.y);
        ffma2(sC[4], ccC, qc.x); ffma2(sC[5], ccC, qc.y);
        ffma2(sD[0], ccD, qa.x); ffma2(sD[1], ccD, qa.y);
        ffma2(sD[2], ccD, qb.x); ffma2(sD[3], ccD, qb.y);
        ffma2(sD[4], ccD, qc.x); ffma2(sD[5], ccD, qc.y);

        float v = fmaf(di, 0.5f, s1);
        ull v2 = pack2(v, v);
        ffma2(s2p0, v2, dj.x);
        ffma2(s2p1, v2, dj.y);
        s1 += di;
    }

    // Store chunk signature into shared staging (signatory layout)
    {
        float* out = sh_sig[sub];
        if (mm == 0) out[i] = s1;
        U64F2 za; za.u = s2p0;
        U64F2 zb; zb.u = s2p1;
        *(float4*)(out + 12 + i*12 + 4*mm) = make_float4(za.f.x, za.f.y, zb.f.x, zb.f.y);

        float* o3 = out + 156 + (i*12 + 4*mm) * 12;   // 4 rows x 12, contiguous
        U64F2 w0, w1, w2, w3, w4, w5;
#define STORE_ROW(S, OFF) \
        w0.u=S[0]; w1.u=S[1]; w2.u=S[2]; w3.u=S[3]; w4.u=S[4]; w5.u=S[5]; \
        *(float4*)(o3 + (OFF))     = make_float4(w0.f.x, w0.f.y, w1.f.x, w1.f.y); \
        *(float4*)(o3 + (OFF) + 4) = make_float4(w2.f.x, w2.f.y, w3.f.x, w3.f.y); \
        *(float4*)(o3 + (OFF) + 8) = make_float4(w4.f.x, w4.f.y, w5.f.x, w5.f.y);
        STORE_ROW(sA, 0)
        STORE_ROW(sB, 12)
        STORE_ROW(sC, 24)
        STORE_ROW(sD, 36)
#undef STORE_ROW
    }
    __syncthreads();

    // Fused level-1 Chen combine (4 chunks -> 1), all 144 threads
    {
        int ci = tid / 12;
        int cj = tid - ci * 12;

        float a1 = sh_sig[0][ci];
        float a2 = sh_sig[0][12 + tid];
        float a3[12];
        {
            const float* p = sh_sig[0] + 156 + tid * 12;
            float4 v0 = *(const float4*)p;
            float4 v1 = *(const float4*)(p + 4);
            float4 v2 = *(const float4*)(p + 8);
            a3[0]=v0.x; a3[1]=v0.y; a3[2]=v0.z;  a3[3]=v0.w;
            a3[4]=v1.x; a3[5]=v1.y; a3[6]=v1.z;  a3[7]=v1.w;
            a3[8]=v2.x; a3[9]=v2.y; a3[10]=v2.z; a3[11]=v2.w;
        }

#pragma unroll
        for (int cc = 1; cc < 4; cc++) {
            const float* Bp = sh_sig[cc];
            float4 b1a = *(const float4*)(Bp);
            float4 b1b = *(const float4*)(Bp + 4);
            float4 b1c = *(const float4*)(Bp + 8);
            float b1i = Bp[ci];
            float b1j = Bp[cj];
            float b2s = Bp[12 + tid];
            const float* r2 = Bp + 12 + cj * 12;
            float4 r2a = *(const float4*)(r2);
            float4 r2b = *(const float4*)(r2 + 4);
            float4 r2c = *(const float4*)(r2 + 8);
            const float* p3 = Bp + 156 + tid * 12;
            float4 b3a = *(const float4*)(p3);
            float4 b3b = *(const float4*)(p3 + 4);
            float4 b3c = *(const float4*)(p3 + 8);

            a3[0]  += b3a.x + a1*r2a.x + a2*b1a.x;
            a3[1]  += b3a.y + a1*r2a.y + a2*b1a.y;
            a3[2]  += b3a.z + a1*r2a.z + a2*b1a.z;
            a3[3]  += b3a.w + a1*r2a.w + a2*b1a.w;
            a3[4]  += b3b.x + a1*r2b.x + a2*b1b.x;
            a3[5]  += b3b.y + a1*r2b.y + a2*b1b.y;
            a3[6]  += b3b.z + a1*r2b.z + a2*b1b.z;
            a3[7]  += b3b.w + a1*r2b.w + a2*b1b.w;
            a3[8]  += b3c.x + a1*r2c.x + a2*b1c.x;
            a3[9]  += b3c.y + a1*r2c.y + a2*b1c.y;
            a3[10] += b3c.z + a1*r2c.z + a2*b1c.z;
            a3[11] += b3c.w + a1*r2c.w + a2*b1c.w;
            a2 += b2s + a1 * b1j;     // uses OLD a1
            a1 += b1i;
        }

        float* out = g_mid + (size_t)blockIdx.x * SIGC;
        if (cj == 0) out[ci] = a1;
        out[12 + tid] = a2;
        float* o3 = out + 156 + tid * 12;
        *(float4*)(o3)     = make_float4(a3[0], a3[1], a3[2], a3[3]);
        *(float4*)(o3 + 4) = make_float4(a3[4], a3[5], a3[6], a3[7]);
        *(float4*)(o3 + 8) = make_float4(a3[8], a3[9], a3[10], a3[11]);
    }
}

// ---------------------------------------------------------------------------
// Kernel 2: level-2 Chen combine (8 mids -> final signature per path)
// ---------------------------------------------------------------------------
__global__ __launch_bounds__(160) void sig_combine2_kernel()
{
    int tid = threadIdx.x;
    if (tid >= 144) return;
    int i = tid / 12;
    int j = tid - i * 12;

    const float* base = g_mid + (size_t)blockIdx.x * MIDS_PER_PATH * SIGC;

    float a1 = base[i];
    float a2 = base[12 + tid];
    float a3[12];
    {
        const float* p = base + 156 + tid * 12;
        float4 v0 = *(const float4*)p;
        float4 v1 = *(const float4*)(p + 4);
        float4 v2 = *(const float4*)(p + 8);
        a3[0]=v0.x; a3[1]=v0.y; a3[2]=v0.z;  a3[3]=v0.w;
        a3[4]=v1.x; a3[5]=v1.y; a3[6]=v1.z;  a3[7]=v1.w;
        a3[8]=v2.x; a3[9]=v2.y; a3[10]=v2.z; a3[11]=v2.w;
    }

#pragma unroll
    for (int c = 1; c < MIDS_PER_PATH; c++) {
        const float* Bp = base + (size_t)c * SIGC;
        float4 b1a = *(const float4*)(Bp);
        float4 b1b = *(const float4*)(Bp + 4);
        float4 b1c = *(const float4*)(Bp + 8);
        float b1i = Bp[i];
        float b1j = Bp[j];
        float b2s = Bp[12 + tid];
        const float* r2 = Bp + 12 + j * 12;
        float4 r2a = *(const float4*)(r2);
        float4 r2b = *(const float4*)(r2 + 4);
        float4 r2c = *(const float4*)(r2 + 8);
        const float* p3 = Bp + 156 + tid * 12;
        float4 b3a = *(const float4*)(p3);
        float4 b3b = *(const float4*)(p3 + 4);
        float4 b3c = *(const float4*)(p3 + 8);

        a3[0]  += b3a.x + a1*r2a.x + a2*b1a.x;
        a3[1]  += b3a.y + a1*r2a.y + a2*b1a.y;
        a3[2]  += b3a.z + a1*r2a.z + a2*b1a.z;
        a3[3]  += b3a.w + a1*r2a.w + a2*b1a.w;
        a3[4]  += b3b.x + a1*r2b.x + a2*b1b.x;
        a3[5]  += b3b.y + a1*r2b.y + a2*b1b.y;
        a3[6]  += b3b.z + a1*r2b.z + a2*b1b.z;
        a3[7]  += b3b.w + a1*r2b.w + a2*b1b.w;
        a3[8]  += b3c.x + a1*r2c.x + a2*b1c.x;
        a3[9]  += b3c.y + a1*r2c.y + a2*b1c.y;
        a3[10] += b3c.z + a1*r2c.z + a2*b1c.z;
        a3[11] += b3c.w + a1*r2c.w + a2*b1c.w;
        a2 += b2s + a1 * b1j;
        a1 += b1i;
    }

    float* out = g_sig + (size_t)blockIdx.x * SIGC;
    if (j == 0) out[i] = a1;
    out[12 + tid] = a2;
    float* o3 = out + 156 + tid * 12;
    *(float4*)(o3)     = make_float4(a3[0], a3[1], a3[2], a3[3]);
    *(float4*)(o3 + 4) = make_float4(a3[4], a3[5], a3[6], a3[7]);
    *(float4*)(o3 + 8) = make_float4(a3[8], a3[9], a3[10], a3[11]);
}

// ---------------------------------------------------------------------------
// Kernel 3: one block per output element (b,o):
//   out[b][o] = sigmoid( sig[b] . lin_w[o] + lin_b[o] )
// ---------------------------------------------------------------------------
#define SIG2  (2 * SIGC)        // 3768
#define SIG2V (SIG2 / 4)        // 942 float4s

__global__ __launch_bounds__(128) void sig_out_kernel(
    const float* __restrict__ lin_w, const float* __restrict__ lin_b,
    float* __restrict__ out)
{
    int b = blockIdx.x >> 5;
    int o = blockIdx.x & 31;
    int tid = threadIdx.x;

    const float4* wr = (const float4*)(lin_w + (size_t)o * SIG2);
    const float4* sg = (const float4*)(g_sig + (size_t)b * SIG2);

    float acc = 0.f;
#pragma unroll
    for (int it = 0; it < 8; it++) {
        int m = tid + it * 128;
        if (m < SIG2V) {
            float4 w = __ldg(wr + m);
            float4 s = __ldg(sg + m);
            acc = fmaf(w.x, s.x, acc);
            acc = fmaf(w.y, s.y, acc);
            acc = fmaf(w.z, s.z, acc);
            acc = fmaf(w.w, s.w, acc);
        }
    }

#pragma unroll
    for (int off = 16; off; off >>= 1)
        acc += __shfl_down_sync(0xffffffffu, acc, off);

    __shared__ float sh[4];
    int warp = tid >> 5;
    int lane = tid & 31;
    if (lane == 0) sh[warp] = acc;
    __syncthreads();

    if (tid == 0) {
        float z = sh[0] + sh[1] + sh[2] + sh[3] + lin_b[o];
        out[b * 32 + o] = 1.0f / (1.0f + expf(-z));
    }
}

// ---------------------------------------------------------------------------
extern "C" void kernel_launch(void* const* d_in, const int* in_sizes, int n_in,
                              void* d_out, int out_size)
{
    const float* x     = (const float*)d_in[0];  // (32,1024,3)
    const float* aug_w = (const float*)d_in[1];  // (2,8,3)
    // d_in[2] = aug_b — unused (bias cancels in path increments)
    const float* lin_w = (const float*)d_in[3];  // (32, 3768)
    const float* lin_b = (const float*)d_in[4];  // (32,)
    float* out = (float*)d_out;                  // (32,32)

    sig_chunk4_kernel<<<512, 144>>>(x, aug_w);
    sig_combine2_kernel<<<NBG, 160>>>();
    sig_out_kernel<<<B_ * 32, 128>>>(lin_w, lin_b, out);
}